// round 14
// baseline (speedup 1.0000x reference)
#include <cuda_runtime.h>
#include <cuda_fp16.h>
#include <math.h>

#define NN 50000
#define DD 128
#define EE 625000
#define ET (EE + NN)          // edges + self loops
#define NEG_SLOPE 0.2f
#define C0_ROWS 25088         // chunk 0: 196 GEMM blocks; chunk 1: rest

// ---------------- scratch (device globals; no allocation allowed) ----------
__device__ __align__(16) __half g_hh1[NN * DD]; // layer-1 h (fp16)
__device__ __align__(16) __half g_hh2[NN * DD]; // layer-2 h (fp16)
__device__ __align__(16) float g_x1[NN * DD];   // layer-1 output
__device__ __align__(16) float g_ssrc1[NN];
__device__ __align__(16) float g_sdst1[NN];
__device__ __align__(16) float g_ssrc2[NN];
__device__ __align__(16) float g_sdst2[NN];
__device__ __align__(16) int g_deg[NN];
__device__ __align__(16) int g_off[NN + 4];
__device__ __align__(16) int g_cnt[NN + 4];
__device__ __align__(16) int g_csr_src[ET + 64];

// ---------------- GEMM + fused scores ---------------------------------------
__global__ void gemm128(const float* __restrict__ X, const float* __restrict__ W,
                        __half* __restrict__ Hh,
                        const float* __restrict__ a_src,
                        const float* __restrict__ a_dst,
                        float* __restrict__ ssrc, float* __restrict__ sdst,
                        int row_base) {
    extern __shared__ float smem[];
    float* xs = smem;                 // [128][128]
    float* ws = smem + 128 * 128;     // [128][128]
    const int tid = threadIdx.x;
    const int row0 = row_base + blockIdx.x * 128;

    for (int i = tid * 4; i < 128 * 128; i += 256 * 4) {
        int r = i >> 7, c = i & 127;
        int gr = row0 + r;
        float4 xv = (gr < NN) ? *(const float4*)(X + (size_t)gr * DD + c)
                              : make_float4(0.f, 0.f, 0.f, 0.f);
        *(float4*)&xs[r * 128 + c] = xv;
        *(float4*)&ws[r * 128 + c] = *(const float4*)(W + r * 128 + c);
    }
    __syncthreads();

    const int ty = tid >> 4;   // 0..15
    const int tx = tid & 15;   // 0..15

    unsigned long long acc[8][4];
#pragma unroll
    for (int i = 0; i < 8; i++)
#pragma unroll
        for (int j = 0; j < 4; j++) acc[i][j] = 0ull;

    for (int k = 0; k < 128; k++) {
        float a[8];
        unsigned long long b2[4];
#pragma unroll
        for (int i = 0; i < 8; i++) a[i] = xs[(ty * 8 + i) * 128 + k];
        const unsigned long long* wrow =
            (const unsigned long long*)&ws[k * 128 + tx * 8];
#pragma unroll
        for (int j = 0; j < 4; j++) b2[j] = wrow[j];
#pragma unroll
        for (int i = 0; i < 8; i++) {
            unsigned long long a2;
            asm("mov.b64 %0, {%1, %1};" : "=l"(a2) : "r"(__float_as_uint(a[i])));
#pragma unroll
            for (int j = 0; j < 4; j++)
                asm("fma.rn.f32x2 %0, %1, %2, %0;"
                    : "+l"(acc[i][j]) : "l"(a2), "l"(b2[j]));
        }
    }

    float accf[8][8];
#pragma unroll
    for (int i = 0; i < 8; i++)
#pragma unroll
        for (int j = 0; j < 4; j++)
            asm("mov.b64 {%0, %1}, %2;"
                : "=f"(accf[i][2 * j]), "=f"(accf[i][2 * j + 1]) : "l"(acc[i][j]));

#pragma unroll
    for (int i = 0; i < 8; i++) {
        int r = row0 + ty * 8 + i;
        if (r < NN) {
            __half2 hp[4];
#pragma unroll
            for (int j = 0; j < 4; j++)
                hp[j] = __floats2half2_rn(accf[i][2 * j], accf[i][2 * j + 1]);
            *(uint4*)(Hh + (size_t)r * DD + tx * 8) = *(uint4*)hp;
        }
    }

    // fused scores (fp32)
    float asv[8], adv[8];
    *(float4*)&asv[0] = *(const float4*)(a_src + tx * 8);
    *(float4*)&asv[4] = *(const float4*)(a_src + tx * 8 + 4);
    *(float4*)&adv[0] = *(const float4*)(a_dst + tx * 8);
    *(float4*)&adv[4] = *(const float4*)(a_dst + tx * 8 + 4);

    __syncthreads();
    float* red_s = xs;                // [128][16]
    float* red_d = xs + 128 * 16;     // [128][16]
#pragma unroll
    for (int i = 0; i < 8; i++) {
        float ssp = 0.f, sdp = 0.f;
#pragma unroll
        for (int j = 0; j < 8; j++) {
            ssp += accf[i][j] * asv[j];
            sdp += accf[i][j] * adv[j];
        }
        red_s[(ty * 8 + i) * 16 + tx] = ssp;
        red_d[(ty * 8 + i) * 16 + tx] = sdp;
    }
    __syncthreads();
    if (tid < 128) {
        int r = row0 + tid;
        if (r < NN) {
            float ss = 0.f, sd = 0.f;
#pragma unroll
            for (int t = 0; t < 16; t++) {
                ss += red_s[tid * 16 + t];
                sd += red_d[tid * 16 + t];
            }
            ssrc[r] = ss;
            sdst[r] = sd;
        }
    }
}

// ---------------- CSR build (R8 version — known good) ------------------------
__global__ void zero_deg() {
    int i = blockIdx.x * blockDim.x + threadIdx.x;
    if (i < NN) g_deg[i] = 0;
}

__global__ void csr_hist(const int* __restrict__ ei) {
    int i = blockIdx.x * blockDim.x + threadIdx.x;
    if (i >= ET) return;
    int d = (i < EE) ? ei[EE + i] : (i - EE);
    atomicAdd(&g_deg[d], 1);
}

__global__ void csr_scan() {
    __shared__ int warp_sums[32];
    __shared__ int s_carry;
    const int tid = threadIdx.x, lane = tid & 31, wid = tid >> 5;
    if (tid == 0) s_carry = 0;
    __syncthreads();
    for (int base = 0; base < NN; base += 4096) {
        int i0 = base + tid * 4;
        int4 v = make_int4(0, 0, 0, 0);
        if (i0 + 3 < NN) v = *(const int4*)&g_deg[i0];
        else {
            if (i0 + 0 < NN) v.x = g_deg[i0 + 0];
            if (i0 + 1 < NN) v.y = g_deg[i0 + 1];
            if (i0 + 2 < NN) v.z = g_deg[i0 + 2];
            if (i0 + 3 < NN) v.w = g_deg[i0 + 3];
        }
        int tsum = v.x + v.y + v.z + v.w;
        int sv = tsum;
#pragma unroll
        for (int o = 1; o < 32; o <<= 1) {
            int t = __shfl_up_sync(0xffffffffu, sv, o);
            if (lane >= o) sv += t;
        }
        if (lane == 31) warp_sums[wid] = sv;
        __syncthreads();
        if (wid == 0) {
            int ws = warp_sums[lane];
#pragma unroll
            for (int o = 1; o < 32; o <<= 1) {
                int t = __shfl_up_sync(0xffffffffu, ws, o);
                if (lane >= o) ws += t;
            }
            warp_sums[lane] = ws;
        }
        __syncthreads();
        int excl = s_carry + (sv - tsum) + (wid > 0 ? warp_sums[wid - 1] : 0);
        int4 o4;
        o4.x = excl;
        o4.y = o4.x + v.x;
        o4.z = o4.y + v.y;
        o4.w = o4.z + v.z;
        if (i0 + 3 < NN) {
            *(int4*)&g_off[i0] = o4;
            *(int4*)&g_cnt[i0] = o4;
        } else {
            if (i0 + 0 < NN) { g_off[i0 + 0] = o4.x; g_cnt[i0 + 0] = o4.x; }
            if (i0 + 1 < NN) { g_off[i0 + 1] = o4.y; g_cnt[i0 + 1] = o4.y; }
            if (i0 + 2 < NN) { g_off[i0 + 2] = o4.z; g_cnt[i0 + 2] = o4.z; }
            if (i0 + 3 < NN) { g_off[i0 + 3] = o4.w; g_cnt[i0 + 3] = o4.w; }
        }
        int chunk_total = warp_sums[31];
        __syncthreads();
        if (tid == 0) s_carry += chunk_total;
        __syncthreads();
    }
    if (tid == 0) g_off[NN] = s_carry;
}

__global__ void csr_scatter(const int* __restrict__ ei) {
    int i = blockIdx.x * blockDim.x + threadIdx.x;
    if (i >= ET) return;
    int s, d;
    if (i < EE) { s = ei[i]; d = ei[EE + i]; }
    else        { s = i - EE; d = s; }
    int pos = atomicAdd(&g_cnt[d], 1);
    g_csr_src[pos] = s;
}

// ---------------- aggregation: warp per dst node, fp16 gather ----------------
__global__ void aggregate(const __half* __restrict__ Hh,
                          const float* __restrict__ ssrc,
                          const float* __restrict__ sdst,
                          const float* __restrict__ b,
                          float* __restrict__ out, int do_relu,
                          int node_base, int node_count) {
    int node = node_base + ((blockIdx.x * blockDim.x + threadIdx.x) >> 5);
    int lane = threadIdx.x & 31;
    if (node >= node_base + node_count || node >= NN) return;
    const int beg = g_off[node], end = g_off[node + 1];
    const float sdv = sdst[node];

    float4 acc = make_float4(0.f, 0.f, 0.f, 0.f);
    float z = 0.f;
    int j = beg;

    for (; j + 8 <= end; j += 8) {
        int s[8];
#pragma unroll
        for (int i = 0; i < 8; i++) s[i] = __ldg(&g_csr_src[j + i]);
        float e[8];
#pragma unroll
        for (int i = 0; i < 8; i++) e[i] = ssrc[s[i]] + sdv;
        uint2 raw[8];
#pragma unroll
        for (int i = 0; i < 8; i++)
            raw[i] = *(const uint2*)(Hh + (size_t)s[i] * DD + lane * 4);
        float p[8];
#pragma unroll
        for (int i = 0; i < 8; i++) {
            float ee = e[i] > 0.f ? e[i] : NEG_SLOPE * e[i];
            p[i] = __expf(ee);
            z += p[i];
        }
#pragma unroll
        for (int i = 0; i < 8; i++) {
            float2 f01 = __half22float2(*(__half2*)&raw[i].x);
            float2 f23 = __half22float2(*(__half2*)&raw[i].y);
            acc.x += p[i] * f01.x; acc.y += p[i] * f01.y;
            acc.z += p[i] * f23.x; acc.w += p[i] * f23.y;
        }
    }
    for (; j + 4 <= end; j += 4) {
        int s0 = g_csr_src[j + 0], s1 = g_csr_src[j + 1];
        int s2 = g_csr_src[j + 2], s3 = g_csr_src[j + 3];
        float e0 = ssrc[s0] + sdv, e1 = ssrc[s1] + sdv;
        float e2 = ssrc[s2] + sdv, e3 = ssrc[s3] + sdv;
        uint2 r0 = *(const uint2*)(Hh + (size_t)s0 * DD + lane * 4);
        uint2 r1 = *(const uint2*)(Hh + (size_t)s1 * DD + lane * 4);
        uint2 r2 = *(const uint2*)(Hh + (size_t)s2 * DD + lane * 4);
        uint2 r3 = *(const uint2*)(Hh + (size_t)s3 * DD + lane * 4);
        e0 = e0 > 0.f ? e0 : NEG_SLOPE * e0;
        e1 = e1 > 0.f ? e1 : NEG_SLOPE * e1;
        e2 = e2 > 0.f ? e2 : NEG_SLOPE * e2;
        e3 = e3 > 0.f ? e3 : NEG_SLOPE * e3;
        float p0 = __expf(e0), p1 = __expf(e1);
        float p2 = __expf(e2), p3 = __expf(e3);
        z += p0 + p1 + p2 + p3;
        float2 a0 = __half22float2(*(__half2*)&r0.x), b0 = __half22float2(*(__half2*)&r0.y);
        float2 a1 = __half22float2(*(__half2*)&r1.x), b1 = __half22float2(*(__half2*)&r1.y);
        float2 a2 = __half22float2(*(__half2*)&r2.x), b2 = __half22float2(*(__half2*)&r2.y);
        float2 a3 = __half22float2(*(__half2*)&r3.x), b3 = __half22float2(*(__half2*)&r3.y);
        acc.x += p0 * a0.x + p1 * a1.x + p2 * a2.x + p3 * a3.x;
        acc.y += p0 * a0.y + p1 * a1.y + p2 * a2.y + p3 * a3.y;
        acc.z += p0 * b0.x + p1 * b1.x + p2 * b2.x + p3 * b3.x;
        acc.w += p0 * b0.y + p1 * b1.y + p2 * b2.y + p3 * b3.y;
    }
    for (; j < end; j++) {
        int s = g_csr_src[j];
        float e = ssrc[s] + sdv;
        e = e > 0.f ? e : NEG_SLOPE * e;
        float p = __expf(e);
        uint2 raw = *(const uint2*)(Hh + (size_t)s * DD + lane * 4);
        float2 f01 = __half22float2(*(__half2*)&raw.x);
        float2 f23 = __half22float2(*(__half2*)&raw.y);
        z += p;
        acc.x += p * f01.x; acc.y += p * f01.y;
        acc.z += p * f23.x; acc.w += p * f23.y;
    }

    float inv = 1.f / (z + 1e-16f);
    float4 bv = ((const float4*)b)[lane];
    float4 o4 = make_float4(acc.x * inv + bv.x, acc.y * inv + bv.y,
                            acc.z * inv + bv.z, acc.w * inv + bv.w);
    if (do_relu) {
        o4.x = fmaxf(o4.x, 0.f); o4.y = fmaxf(o4.y, 0.f);
        o4.z = fmaxf(o4.z, 0.f); o4.w = fmaxf(o4.w, 0.f);
    }
    ((float4*)(out + (size_t)node * DD))[lane] = o4;
}

// ---------------- host orchestration ----------------------------------------
extern "C" void kernel_launch(void* const* d_in, const int* in_sizes, int n_in,
                              void* d_out, int out_size) {
    const float* x   = (const float*)d_in[0];
    const int*   ei  = (const int*)d_in[1];   // int32 (jax default x64-disabled)
    const float* W1  = (const float*)d_in[2];
    const float* as1 = (const float*)d_in[3];
    const float* ad1 = (const float*)d_in[4];
    const float* b1  = (const float*)d_in[5];
    const float* W2  = (const float*)d_in[6];
    const float* as2 = (const float*)d_in[7];
    const float* ad2 = (const float*)d_in[8];
    const float* b2  = (const float*)d_in[9];
    float*       out = (float*)d_out;

    static cudaStream_t s2 = nullptr;
    static cudaEvent_t ev_fork = nullptr, ev_join = nullptr;
    static cudaEvent_t ev_a0 = nullptr, ev_a1 = nullptr;
    if (!s2) {
        cudaFuncSetAttribute(gemm128, cudaFuncAttributeMaxDynamicSharedMemorySize,
                             2 * 128 * 128 * sizeof(float));
        cudaStreamCreateWithFlags(&s2, cudaStreamNonBlocking);
        cudaEventCreateWithFlags(&ev_fork, cudaEventDisableTiming);
        cudaEventCreateWithFlags(&ev_join, cudaEventDisableTiming);
        cudaEventCreateWithFlags(&ev_a0, cudaEventDisableTiming);
        cudaEventCreateWithFlags(&ev_a1, cudaEventDisableTiming);
    }

    __half *hh1 = nullptr, *hh2 = nullptr;
    float *x1 = nullptr, *ss1 = nullptr, *sd1 = nullptr, *ss2 = nullptr, *sd2 = nullptr;
    cudaGetSymbolAddress((void**)&hh1, g_hh1);
    cudaGetSymbolAddress((void**)&hh2, g_hh2);
    cudaGetSymbolAddress((void**)&x1, g_x1);
    cudaGetSymbolAddress((void**)&ss1, g_ssrc1);
    cudaGetSymbolAddress((void**)&sd1, g_sdst1);
    cudaGetSymbolAddress((void**)&ss2, g_ssrc2);
    cudaGetSymbolAddress((void**)&sd2, g_sdst2);

    const int GEMM_SMEM = 2 * 128 * 128 * sizeof(float);
    const int C1_ROWS = NN - C0_ROWS;
    const int C0_BLK = C0_ROWS / 128;                 // 196
    const int C1_BLK = (C1_ROWS + 127) / 128;         // 195

    // fork: CSR build (independent of GEMM1) on side stream
    cudaEventRecord(ev_fork, 0);
    cudaStreamWaitEvent(s2, ev_fork, 0);
    zero_deg<<<(NN + 255) / 256, 256, 0, s2>>>();
    csr_hist<<<(ET + 255) / 256, 256, 0, s2>>>(ei);
    csr_scan<<<1, 1024, 0, s2>>>();
    csr_scatter<<<(ET + 255) / 256, 256, 0, s2>>>(ei);
    cudaEventRecord(ev_join, s2);

    // layer-1 GEMM (full) overlaps CSR build
    gemm128<<<(NN + 127) / 128, 256, GEMM_SMEM>>>(x, W1, hh1, as1, ad1, ss1, sd1, 0);

    // join CSR before first aggregate
    cudaStreamWaitEvent(0, ev_join, 0);

    // agg1 chunk 0 (full machine)
    aggregate<<<(C0_ROWS * 32 + 255) / 256, 256>>>(hh1, ss1, sd1, b1, x1, 1,
                                                   0, C0_ROWS);
    cudaEventRecord(ev_a0, 0);

    // agg1 chunk 1 on s2, overlapping GEMM2 chunk 0 on stream 0
    cudaStreamWaitEvent(s2, ev_a0, 0);
    aggregate<<<(C1_ROWS * 32 + 255) / 256, 256, 0, s2>>>(hh1, ss1, sd1, b1, x1, 1,
                                                          C0_ROWS, C1_ROWS);
    cudaEventRecord(ev_a1, s2);

    gemm128<<<C0_BLK, 256, GEMM_SMEM>>>(x1, W2, hh2, as2, ad2, ss2, sd2, 0);

    // GEMM2 chunk 1 needs agg1 chunk 1 output
    cudaStreamWaitEvent(0, ev_a1, 0);
    gemm128<<<C1_BLK, 256, GEMM_SMEM>>>(x1, W2, hh2, as2, ad2, ss2, sd2, C0_ROWS);

    // final aggregate (full)
    aggregate<<<(NN * 32 + 255) / 256, 256>>>(hh2, ss2, sd2, b2, out, 0, 0, NN);
}

// round 15
// speedup vs baseline: 1.0002x; 1.0002x over previous
#include <cuda_runtime.h>
#include <cuda_fp16.h>
#include <math.h>

#define NN 50000
#define DD 128
#define EE 625000
#define ET (EE + NN)          // edges + self loops
#define NEG_SLOPE 0.2f
#define C0_ROWS 25088         // chunk 0: 196 GEMM blocks; chunk 1: rest

// ---------------- scratch (device globals; no allocation allowed) ----------
__device__ __align__(16) __half g_hh1[NN * DD]; // layer-1 h (fp16)
__device__ __align__(16) __half g_hh2[NN * DD]; // layer-2 h (fp16)
__device__ __align__(16) float g_x1[NN * DD];   // layer-1 output
__device__ __align__(16) float g_ssrc1[NN];
__device__ __align__(16) float g_sdst1[NN];
__device__ __align__(16) float g_ssrc2[NN];
__device__ __align__(16) float g_sdst2[NN];
__device__ __align__(16) int g_deg[NN];
__device__ __align__(16) int g_off[NN + 4];
__device__ __align__(16) int g_cnt[NN + 4];
__device__ __align__(16) int g_csr_src[ET + 64];

// ---------------- GEMM + fused scores ---------------------------------------
__global__ void gemm128(const float* __restrict__ X, const float* __restrict__ W,
                        __half* __restrict__ Hh,
                        const float* __restrict__ a_src,
                        const float* __restrict__ a_dst,
                        float* __restrict__ ssrc, float* __restrict__ sdst,
                        int row_base) {
    extern __shared__ float smem[];
    float* xs = smem;                 // [128][128]
    float* ws = smem + 128 * 128;     // [128][128]
    const int tid = threadIdx.x;
    const int row0 = row_base + blockIdx.x * 128;

    for (int i = tid * 4; i < 128 * 128; i += 256 * 4) {
        int r = i >> 7, c = i & 127;
        int gr = row0 + r;
        float4 xv = (gr < NN) ? *(const float4*)(X + (size_t)gr * DD + c)
                              : make_float4(0.f, 0.f, 0.f, 0.f);
        *(float4*)&xs[r * 128 + c] = xv;
        *(float4*)&ws[r * 128 + c] = *(const float4*)(W + r * 128 + c);
    }
    __syncthreads();

    const int ty = tid >> 4;   // 0..15
    const int tx = tid & 15;   // 0..15

    unsigned long long acc[8][4];
#pragma unroll
    for (int i = 0; i < 8; i++)
#pragma unroll
        for (int j = 0; j < 4; j++) acc[i][j] = 0ull;

    for (int k = 0; k < 128; k++) {
        float a[8];
        unsigned long long b2[4];
#pragma unroll
        for (int i = 0; i < 8; i++) a[i] = xs[(ty * 8 + i) * 128 + k];
        const unsigned long long* wrow =
            (const unsigned long long*)&ws[k * 128 + tx * 8];
#pragma unroll
        for (int j = 0; j < 4; j++) b2[j] = wrow[j];
#pragma unroll
        for (int i = 0; i < 8; i++) {
            unsigned long long a2;
            asm("mov.b64 %0, {%1, %1};" : "=l"(a2) : "r"(__float_as_uint(a[i])));
#pragma unroll
            for (int j = 0; j < 4; j++)
                asm("fma.rn.f32x2 %0, %1, %2, %0;"
                    : "+l"(acc[i][j]) : "l"(a2), "l"(b2[j]));
        }
    }

    float accf[8][8];
#pragma unroll
    for (int i = 0; i < 8; i++)
#pragma unroll
        for (int j = 0; j < 4; j++)
            asm("mov.b64 {%0, %1}, %2;"
                : "=f"(accf[i][2 * j]), "=f"(accf[i][2 * j + 1]) : "l"(acc[i][j]));

#pragma unroll
    for (int i = 0; i < 8; i++) {
        int r = row0 + ty * 8 + i;
        if (r < NN) {
            __half2 hp[4];
#pragma unroll
            for (int j = 0; j < 4; j++)
                hp[j] = __floats2half2_rn(accf[i][2 * j], accf[i][2 * j + 1]);
            *(uint4*)(Hh + (size_t)r * DD + tx * 8) = *(uint4*)hp;
        }
    }

    // fused scores (fp32)
    float asv[8], adv[8];
    *(float4*)&asv[0] = *(const float4*)(a_src + tx * 8);
    *(float4*)&asv[4] = *(const float4*)(a_src + tx * 8 + 4);
    *(float4*)&adv[0] = *(const float4*)(a_dst + tx * 8);
    *(float4*)&adv[4] = *(const float4*)(a_dst + tx * 8 + 4);

    __syncthreads();
    float* red_s = xs;                // [128][16]
    float* red_d = xs + 128 * 16;     // [128][16]
#pragma unroll
    for (int i = 0; i < 8; i++) {
        float ssp = 0.f, sdp = 0.f;
#pragma unroll
        for (int j = 0; j < 8; j++) {
            ssp += accf[i][j] * asv[j];
            sdp += accf[i][j] * adv[j];
        }
        red_s[(ty * 8 + i) * 16 + tx] = ssp;
        red_d[(ty * 8 + i) * 16 + tx] = sdp;
    }
    __syncthreads();
    if (tid < 128) {
        int r = row0 + tid;
        if (r < NN) {
            float ss = 0.f, sd = 0.f;
#pragma unroll
            for (int t = 0; t < 16; t++) {
                ss += red_s[tid * 16 + t];
                sd += red_d[tid * 16 + t];
            }
            ssrc[r] = ss;
            sdst[r] = sd;
        }
    }
}

// ---------------- CSR build (R8 version — known good) ------------------------
__global__ void zero_deg() {
    int i = blockIdx.x * blockDim.x + threadIdx.x;
    if (i < NN) g_deg[i] = 0;
}

__global__ void csr_hist(const int* __restrict__ ei) {
    int i = blockIdx.x * blockDim.x + threadIdx.x;
    if (i >= ET) return;
    int d = (i < EE) ? ei[EE + i] : (i - EE);
    atomicAdd(&g_deg[d], 1);
}

__global__ void csr_scan() {
    __shared__ int warp_sums[32];
    __shared__ int s_carry;
    const int tid = threadIdx.x, lane = tid & 31, wid = tid >> 5;
    if (tid == 0) s_carry = 0;
    __syncthreads();
    for (int base = 0; base < NN; base += 4096) {
        int i0 = base + tid * 4;
        int4 v = make_int4(0, 0, 0, 0);
        if (i0 + 3 < NN) v = *(const int4*)&g_deg[i0];
        else {
            if (i0 + 0 < NN) v.x = g_deg[i0 + 0];
            if (i0 + 1 < NN) v.y = g_deg[i0 + 1];
            if (i0 + 2 < NN) v.z = g_deg[i0 + 2];
            if (i0 + 3 < NN) v.w = g_deg[i0 + 3];
        }
        int tsum = v.x + v.y + v.z + v.w;
        int sv = tsum;
#pragma unroll
        for (int o = 1; o < 32; o <<= 1) {
            int t = __shfl_up_sync(0xffffffffu, sv, o);
            if (lane >= o) sv += t;
        }
        if (lane == 31) warp_sums[wid] = sv;
        __syncthreads();
        if (wid == 0) {
            int ws = warp_sums[lane];
#pragma unroll
            for (int o = 1; o < 32; o <<= 1) {
                int t = __shfl_up_sync(0xffffffffu, ws, o);
                if (lane >= o) ws += t;
            }
            warp_sums[lane] = ws;
        }
        __syncthreads();
        int excl = s_carry + (sv - tsum) + (wid > 0 ? warp_sums[wid - 1] : 0);
        int4 o4;
        o4.x = excl;
        o4.y = o4.x + v.x;
        o4.z = o4.y + v.y;
        o4.w = o4.z + v.z;
        if (i0 + 3 < NN) {
            *(int4*)&g_off[i0] = o4;
            *(int4*)&g_cnt[i0] = o4;
        } else {
            if (i0 + 0 < NN) { g_off[i0 + 0] = o4.x; g_cnt[i0 + 0] = o4.x; }
            if (i0 + 1 < NN) { g_off[i0 + 1] = o4.y; g_cnt[i0 + 1] = o4.y; }
            if (i0 + 2 < NN) { g_off[i0 + 2] = o4.z; g_cnt[i0 + 2] = o4.z; }
            if (i0 + 3 < NN) { g_off[i0 + 3] = o4.w; g_cnt[i0 + 3] = o4.w; }
        }
        int chunk_total = warp_sums[31];
        __syncthreads();
        if (tid == 0) s_carry += chunk_total;
        __syncthreads();
    }
    if (tid == 0) g_off[NN] = s_carry;
}

__global__ void csr_scatter(const int* __restrict__ ei) {
    int i = blockIdx.x * blockDim.x + threadIdx.x;
    if (i >= ET) return;
    int s, d;
    if (i < EE) { s = ei[i]; d = ei[EE + i]; }
    else        { s = i - EE; d = s; }
    int pos = atomicAdd(&g_cnt[d], 1);
    g_csr_src[pos] = s;
}

// ---------------- aggregation: warp per dst node, fp16 gather ----------------
__global__ void aggregate(const __half* __restrict__ Hh,
                          const float* __restrict__ ssrc,
                          const float* __restrict__ sdst,
                          const float* __restrict__ b,
                          float* __restrict__ out, int do_relu,
                          int node_base, int node_count) {
    int node = node_base + ((blockIdx.x * blockDim.x + threadIdx.x) >> 5);
    int lane = threadIdx.x & 31;
    if (node >= node_base + node_count || node >= NN) return;
    const int beg = g_off[node], end = g_off[node + 1];
    const float sdv = sdst[node];

    float4 acc = make_float4(0.f, 0.f, 0.f, 0.f);
    float z = 0.f;
    int j = beg;

    for (; j + 8 <= end; j += 8) {
        int s[8];
#pragma unroll
        for (int i = 0; i < 8; i++) s[i] = __ldg(&g_csr_src[j + i]);
        float e[8];
#pragma unroll
        for (int i = 0; i < 8; i++) e[i] = ssrc[s[i]] + sdv;
        uint2 raw[8];
#pragma unroll
        for (int i = 0; i < 8; i++)
            raw[i] = *(const uint2*)(Hh + (size_t)s[i] * DD + lane * 4);
        float p[8];
#pragma unroll
        for (int i = 0; i < 8; i++) {
            float ee = e[i] > 0.f ? e[i] : NEG_SLOPE * e[i];
            p[i] = __expf(ee);
            z += p[i];
        }
#pragma unroll
        for (int i = 0; i < 8; i++) {
            float2 f01 = __half22float2(*(__half2*)&raw[i].x);
            float2 f23 = __half22float2(*(__half2*)&raw[i].y);
            acc.x += p[i] * f01.x; acc.y += p[i] * f01.y;
            acc.z += p[i] * f23.x; acc.w += p[i] * f23.y;
        }
    }
    for (; j + 4 <= end; j += 4) {
        int s0 = g_csr_src[j + 0], s1 = g_csr_src[j + 1];
        int s2 = g_csr_src[j + 2], s3 = g_csr_src[j + 3];
        float e0 = ssrc[s0] + sdv, e1 = ssrc[s1] + sdv;
        float e2 = ssrc[s2] + sdv, e3 = ssrc[s3] + sdv;
        uint2 r0 = *(const uint2*)(Hh + (size_t)s0 * DD + lane * 4);
        uint2 r1 = *(const uint2*)(Hh + (size_t)s1 * DD + lane * 4);
        uint2 r2 = *(const uint2*)(Hh + (size_t)s2 * DD + lane * 4);
        uint2 r3 = *(const uint2*)(Hh + (size_t)s3 * DD + lane * 4);
        e0 = e0 > 0.f ? e0 : NEG_SLOPE * e0;
        e1 = e1 > 0.f ? e1 : NEG_SLOPE * e1;
        e2 = e2 > 0.f ? e2 : NEG_SLOPE * e2;
        e3 = e3 > 0.f ? e3 : NEG_SLOPE * e3;
        float p0 = __expf(e0), p1 = __expf(e1);
        float p2 = __expf(e2), p3 = __expf(e3);
        z += p0 + p1 + p2 + p3;
        float2 a0 = __half22float2(*(__half2*)&r0.x), b0 = __half22float2(*(__half2*)&r0.y);
        float2 a1 = __half22float2(*(__half2*)&r1.x), b1 = __half22float2(*(__half2*)&r1.y);
        float2 a2 = __half22float2(*(__half2*)&r2.x), b2 = __half22float2(*(__half2*)&r2.y);
        float2 a3 = __half22float2(*(__half2*)&r3.x), b3 = __half22float2(*(__half2*)&r3.y);
        acc.x += p0 * a0.x + p1 * a1.x + p2 * a2.x + p3 * a3.x;
        acc.y += p0 * a0.y + p1 * a1.y + p2 * a2.y + p3 * a3.y;
        acc.z += p0 * b0.x + p1 * b1.x + p2 * b2.x + p3 * b3.x;
        acc.w += p0 * b0.y + p1 * b1.y + p2 * b2.y + p3 * b3.y;
    }
    for (; j < end; j++) {
        int s = g_csr_src[j];
        float e = ssrc[s] + sdv;
        e = e > 0.f ? e : NEG_SLOPE * e;
        float p = __expf(e);
        uint2 raw = *(const uint2*)(Hh + (size_t)s * DD + lane * 4);
        float2 f01 = __half22float2(*(__half2*)&raw.x);
        float2 f23 = __half22float2(*(__half2*)&raw.y);
        z += p;
        acc.x += p * f01.x; acc.y += p * f01.y;
        acc.z += p * f23.x; acc.w += p * f23.y;
    }

    float inv = 1.f / (z + 1e-16f);
    float4 bv = ((const float4*)b)[lane];
    float4 o4 = make_float4(acc.x * inv + bv.x, acc.y * inv + bv.y,
                            acc.z * inv + bv.z, acc.w * inv + bv.w);
    if (do_relu) {
        o4.x = fmaxf(o4.x, 0.f); o4.y = fmaxf(o4.y, 0.f);
        o4.z = fmaxf(o4.z, 0.f); o4.w = fmaxf(o4.w, 0.f);
    }
    ((float4*)(out + (size_t)node * DD))[lane] = o4;
}

// ---------------- host orchestration ----------------------------------------
extern "C" void kernel_launch(void* const* d_in, const int* in_sizes, int n_in,
                              void* d_out, int out_size) {
    const float* x   = (const float*)d_in[0];
    const int*   ei  = (const int*)d_in[1];   // int32 (jax default x64-disabled)
    const float* W1  = (const float*)d_in[2];
    const float* as1 = (const float*)d_in[3];
    const float* ad1 = (const float*)d_in[4];
    const float* b1  = (const float*)d_in[5];
    const float* W2  = (const float*)d_in[6];
    const float* as2 = (const float*)d_in[7];
    const float* ad2 = (const float*)d_in[8];
    const float* b2  = (const float*)d_in[9];
    float*       out = (float*)d_out;

    static cudaStream_t s2 = nullptr;
    static cudaEvent_t ev_fork = nullptr, ev_join = nullptr;
    static cudaEvent_t ev_a0 = nullptr, ev_a1 = nullptr;
    if (!s2) {
        cudaFuncSetAttribute(gemm128, cudaFuncAttributeMaxDynamicSharedMemorySize,
                             2 * 128 * 128 * sizeof(float));
        cudaStreamCreateWithFlags(&s2, cudaStreamNonBlocking);
        cudaEventCreateWithFlags(&ev_fork, cudaEventDisableTiming);
        cudaEventCreateWithFlags(&ev_join, cudaEventDisableTiming);
        cudaEventCreateWithFlags(&ev_a0, cudaEventDisableTiming);
        cudaEventCreateWithFlags(&ev_a1, cudaEventDisableTiming);
    }

    __half *hh1 = nullptr, *hh2 = nullptr;
    float *x1 = nullptr, *ss1 = nullptr, *sd1 = nullptr, *ss2 = nullptr, *sd2 = nullptr;
    cudaGetSymbolAddress((void**)&hh1, g_hh1);
    cudaGetSymbolAddress((void**)&hh2, g_hh2);
    cudaGetSymbolAddress((void**)&x1, g_x1);
    cudaGetSymbolAddress((void**)&ss1, g_ssrc1);
    cudaGetSymbolAddress((void**)&sd1, g_sdst1);
    cudaGetSymbolAddress((void**)&ss2, g_ssrc2);
    cudaGetSymbolAddress((void**)&sd2, g_sdst2);

    const int GEMM_SMEM = 2 * 128 * 128 * sizeof(float);
    const int C1_ROWS = NN - C0_ROWS;
    const int C0_BLK = C0_ROWS / 128;                 // 196
    const int C1_BLK = (C1_ROWS + 127) / 128;         // 195

    // fork: CSR build (independent of GEMM1) on side stream
    cudaEventRecord(ev_fork, 0);
    cudaStreamWaitEvent(s2, ev_fork, 0);
    zero_deg<<<(NN + 255) / 256, 256, 0, s2>>>();
    csr_hist<<<(ET + 255) / 256, 256, 0, s2>>>(ei);
    csr_scan<<<1, 1024, 0, s2>>>();
    csr_scatter<<<(ET + 255) / 256, 256, 0, s2>>>(ei);
    cudaEventRecord(ev_join, s2);

    // layer-1 GEMM (full) overlaps CSR build
    gemm128<<<(NN + 127) / 128, 256, GEMM_SMEM>>>(x, W1, hh1, as1, ad1, ss1, sd1, 0);

    // join CSR before first aggregate
    cudaStreamWaitEvent(0, ev_join, 0);

    // agg1 chunk 0 (full machine)
    aggregate<<<(C0_ROWS * 32 + 255) / 256, 256>>>(hh1, ss1, sd1, b1, x1, 1,
                                                   0, C0_ROWS);
    cudaEventRecord(ev_a0, 0);

    // agg1 chunk 1 on s2, overlapping GEMM2 chunk 0 on stream 0
    cudaStreamWaitEvent(s2, ev_a0, 0);
    aggregate<<<(C1_ROWS * 32 + 255) / 256, 256, 0, s2>>>(hh1, ss1, sd1, b1, x1, 1,
                                                          C0_ROWS, C1_ROWS);
    cudaEventRecord(ev_a1, s2);

    gemm128<<<C0_BLK, 256, GEMM_SMEM>>>(x1, W2, hh2, as2, ad2, ss2, sd2, 0);

    // GEMM2 chunk 1 needs agg1 chunk 1 output
    cudaStreamWaitEvent(0, ev_a1, 0);
    gemm128<<<C1_BLK, 256, GEMM_SMEM>>>(x1, W2, hh2, as2, ad2, ss2, sd2, C0_ROWS);

    // final aggregate (full)
    aggregate<<<(NN * 32 + 255) / 256, 256>>>(hh2, ss2, sd2, b2, out, 0, 0, NN);
}

// round 16
// speedup vs baseline: 1.0615x; 1.0613x over previous
#include <cuda_runtime.h>
#include <cuda_fp16.h>
#include <math.h>

#define NN 50000
#define DD 128
#define EE 625000
#define ET (EE + NN)          // edges + self loops
#define NEG_SLOPE 0.2f

// ---------------- scratch (device globals; no allocation allowed) ----------
__device__ __align__(16) __half g_hh[NN * DD];  // h = x@W (fp16, gather copy)
__device__ __align__(16) float g_x1[NN * DD];   // layer-1 output (x for layer 2)
__device__ __align__(16) float g_ssrc[NN];
__device__ __align__(16) float g_sdst[NN];
__device__ __align__(16) float g_pe[ET + 8];    // per-edge exp(leakyrelu(e)), CSR order
__device__ __align__(16) int g_deg[NN];
__device__ __align__(16) int g_off[NN + 4];
__device__ __align__(16) int g_cnt[NN + 4];
__device__ __align__(16) int g_csr_src[ET + 64];
__device__ __align__(16) int g_csr_dst[ET + 64];  // dst per CSR slot (for edge_p)

// ---------------- GEMM + fused scores ---------------------------------------
__global__ void gemm128(const float* __restrict__ X, const float* __restrict__ W,
                        __half* __restrict__ Hh,
                        const float* __restrict__ a_src,
                        const float* __restrict__ a_dst) {
    extern __shared__ float smem[];
    float* xs = smem;                 // [128][128]
    float* ws = smem + 128 * 128;     // [128][128]
    const int tid = threadIdx.x;
    const int row0 = blockIdx.x * 128;

    for (int i = tid * 4; i < 128 * 128; i += 256 * 4) {
        int r = i >> 7, c = i & 127;
        int gr = row0 + r;
        float4 xv = (gr < NN) ? *(const float4*)(X + (size_t)gr * DD + c)
                              : make_float4(0.f, 0.f, 0.f, 0.f);
        *(float4*)&xs[r * 128 + c] = xv;
        *(float4*)&ws[r * 128 + c] = *(const float4*)(W + r * 128 + c);
    }
    __syncthreads();

    const int ty = tid >> 4;   // 0..15
    const int tx = tid & 15;   // 0..15

    unsigned long long acc[8][4];
#pragma unroll
    for (int i = 0; i < 8; i++)
#pragma unroll
        for (int j = 0; j < 4; j++) acc[i][j] = 0ull;

    for (int k = 0; k < 128; k++) {
        float a[8];
        unsigned long long b2[4];
#pragma unroll
        for (int i = 0; i < 8; i++) a[i] = xs[(ty * 8 + i) * 128 + k];
        const unsigned long long* wrow =
            (const unsigned long long*)&ws[k * 128 + tx * 8];
#pragma unroll
        for (int j = 0; j < 4; j++) b2[j] = wrow[j];
#pragma unroll
        for (int i = 0; i < 8; i++) {
            unsigned long long a2;
            asm("mov.b64 %0, {%1, %1};" : "=l"(a2) : "r"(__float_as_uint(a[i])));
#pragma unroll
            for (int j = 0; j < 4; j++)
                asm("fma.rn.f32x2 %0, %1, %2, %0;"
                    : "+l"(acc[i][j]) : "l"(a2), "l"(b2[j]));
        }
    }

    float accf[8][8];
#pragma unroll
    for (int i = 0; i < 8; i++)
#pragma unroll
        for (int j = 0; j < 4; j++)
            asm("mov.b64 {%0, %1}, %2;"
                : "=f"(accf[i][2 * j]), "=f"(accf[i][2 * j + 1]) : "l"(acc[i][j]));

#pragma unroll
    for (int i = 0; i < 8; i++) {
        int r = row0 + ty * 8 + i;
        if (r < NN) {
            __half2 hp[4];
#pragma unroll
            for (int j = 0; j < 4; j++)
                hp[j] = __floats2half2_rn(accf[i][2 * j], accf[i][2 * j + 1]);
            *(uint4*)(Hh + (size_t)r * DD + tx * 8) = *(uint4*)hp;
        }
    }

    // fused scores (fp32)
    float asv[8], adv[8];
    *(float4*)&asv[0] = *(const float4*)(a_src + tx * 8);
    *(float4*)&asv[4] = *(const float4*)(a_src + tx * 8 + 4);
    *(float4*)&adv[0] = *(const float4*)(a_dst + tx * 8);
    *(float4*)&adv[4] = *(const float4*)(a_dst + tx * 8 + 4);

    __syncthreads();
    float* red_s = xs;                // [128][16]
    float* red_d = xs + 128 * 16;     // [128][16]
#pragma unroll
    for (int i = 0; i < 8; i++) {
        float ssp = 0.f, sdp = 0.f;
#pragma unroll
        for (int j = 0; j < 8; j++) {
            ssp += accf[i][j] * asv[j];
            sdp += accf[i][j] * adv[j];
        }
        red_s[(ty * 8 + i) * 16 + tx] = ssp;
        red_d[(ty * 8 + i) * 16 + tx] = sdp;
    }
    __syncthreads();
    if (tid < 128) {
        int r = row0 + tid;
        if (r < NN) {
            float ss = 0.f, sd = 0.f;
#pragma unroll
            for (int t = 0; t < 16; t++) {
                ss += red_s[tid * 16 + t];
                sd += red_d[tid * 16 + t];
            }
            g_ssrc[r] = ss;
            g_sdst[r] = sd;
        }
    }
}

// ---------------- CSR build (R8 version — known good) ------------------------
__global__ void zero_deg() {
    int i = blockIdx.x * blockDim.x + threadIdx.x;
    if (i < NN) g_deg[i] = 0;
}

__global__ void csr_hist(const int* __restrict__ ei) {
    int i = blockIdx.x * blockDim.x + threadIdx.x;
    if (i >= ET) return;
    int d = (i < EE) ? ei[EE + i] : (i - EE);
    atomicAdd(&g_deg[d], 1);
}

__global__ void csr_scan() {
    __shared__ int warp_sums[32];
    __shared__ int s_carry;
    const int tid = threadIdx.x, lane = tid & 31, wid = tid >> 5;
    if (tid == 0) s_carry = 0;
    __syncthreads();
    for (int base = 0; base < NN; base += 4096) {
        int i0 = base + tid * 4;
        int4 v = make_int4(0, 0, 0, 0);
        if (i0 + 3 < NN) v = *(const int4*)&g_deg[i0];
        else {
            if (i0 + 0 < NN) v.x = g_deg[i0 + 0];
            if (i0 + 1 < NN) v.y = g_deg[i0 + 1];
            if (i0 + 2 < NN) v.z = g_deg[i0 + 2];
            if (i0 + 3 < NN) v.w = g_deg[i0 + 3];
        }
        int tsum = v.x + v.y + v.z + v.w;
        int sv = tsum;
#pragma unroll
        for (int o = 1; o < 32; o <<= 1) {
            int t = __shfl_up_sync(0xffffffffu, sv, o);
            if (lane >= o) sv += t;
        }
        if (lane == 31) warp_sums[wid] = sv;
        __syncthreads();
        if (wid == 0) {
            int ws = warp_sums[lane];
#pragma unroll
            for (int o = 1; o < 32; o <<= 1) {
                int t = __shfl_up_sync(0xffffffffu, ws, o);
                if (lane >= o) ws += t;
            }
            warp_sums[lane] = ws;
        }
        __syncthreads();
        int excl = s_carry + (sv - tsum) + (wid > 0 ? warp_sums[wid - 1] : 0);
        int4 o4;
        o4.x = excl;
        o4.y = o4.x + v.x;
        o4.z = o4.y + v.y;
        o4.w = o4.z + v.z;
        if (i0 + 3 < NN) {
            *(int4*)&g_off[i0] = o4;
            *(int4*)&g_cnt[i0] = o4;
        } else {
            if (i0 + 0 < NN) { g_off[i0 + 0] = o4.x; g_cnt[i0 + 0] = o4.x; }
            if (i0 + 1 < NN) { g_off[i0 + 1] = o4.y; g_cnt[i0 + 1] = o4.y; }
            if (i0 + 2 < NN) { g_off[i0 + 2] = o4.z; g_cnt[i0 + 2] = o4.z; }
            if (i0 + 3 < NN) { g_off[i0 + 3] = o4.w; g_cnt[i0 + 3] = o4.w; }
        }
        int chunk_total = warp_sums[31];
        __syncthreads();
        if (tid == 0) s_carry += chunk_total;
        __syncthreads();
    }
    if (tid == 0) g_off[NN] = s_carry;
}

__global__ void csr_scatter(const int* __restrict__ ei) {
    int i = blockIdx.x * blockDim.x + threadIdx.x;
    if (i >= ET) return;
    int s, d;
    if (i < EE) { s = ei[i]; d = ei[EE + i]; }
    else        { s = i - EE; d = s; }
    int pos = atomicAdd(&g_cnt[d], 1);
    g_csr_src[pos] = s;
    g_csr_dst[pos] = d;
}

// ---------------- per-edge attention weight (edge-parallel, coalesced) -------
__global__ void edge_p() {
    int i = blockIdx.x * blockDim.x + threadIdx.x;
    if (i >= ET) return;
    int s = g_csr_src[i];
    int d = g_csr_dst[i];
    float e = g_ssrc[s] + g_sdst[d];
    e = e > 0.f ? e : NEG_SLOPE * e;
    g_pe[i] = __expf(e);      // |e| <~ 12 for this data; no max-shift needed
}

// ---------------- aggregation: warp per dst node, fp16 gather ----------------
// Inner loop reads sequential csr_src + pe (L1-hit dominated) + H row gathers.
__global__ void aggregate(const __half* __restrict__ Hh,
                          const float* __restrict__ b,
                          float* __restrict__ out, int do_relu) {
    int node = (blockIdx.x * blockDim.x + threadIdx.x) >> 5;
    int lane = threadIdx.x & 31;
    if (node >= NN) return;
    const int beg = g_off[node], end = g_off[node + 1];

    float4 acc = make_float4(0.f, 0.f, 0.f, 0.f);
    float z = 0.f;
    int j = beg;

    // 8-wide pipelined main loop
    for (; j + 8 <= end; j += 8) {
        int s[8];
        float p[8];
#pragma unroll
        for (int i = 0; i < 8; i++) s[i] = __ldg(&g_csr_src[j + i]);
#pragma unroll
        for (int i = 0; i < 8; i++) p[i] = __ldg(&g_pe[j + i]);
        uint2 raw[8];
#pragma unroll
        for (int i = 0; i < 8; i++)
            raw[i] = *(const uint2*)(Hh + (size_t)s[i] * DD + lane * 4);
#pragma unroll
        for (int i = 0; i < 8; i++) {
            z += p[i];
            float2 f01 = __half22float2(*(__half2*)&raw[i].x);
            float2 f23 = __half22float2(*(__half2*)&raw[i].y);
            acc.x += p[i] * f01.x; acc.y += p[i] * f01.y;
            acc.z += p[i] * f23.x; acc.w += p[i] * f23.y;
        }
    }
    // 4-wide mid
    for (; j + 4 <= end; j += 4) {
        int s0 = g_csr_src[j + 0], s1 = g_csr_src[j + 1];
        int s2 = g_csr_src[j + 2], s3 = g_csr_src[j + 3];
        float p0 = __ldg(&g_pe[j + 0]), p1 = __ldg(&g_pe[j + 1]);
        float p2 = __ldg(&g_pe[j + 2]), p3 = __ldg(&g_pe[j + 3]);
        uint2 r0 = *(const uint2*)(Hh + (size_t)s0 * DD + lane * 4);
        uint2 r1 = *(const uint2*)(Hh + (size_t)s1 * DD + lane * 4);
        uint2 r2 = *(const uint2*)(Hh + (size_t)s2 * DD + lane * 4);
        uint2 r3 = *(const uint2*)(Hh + (size_t)s3 * DD + lane * 4);
        z += p0 + p1 + p2 + p3;
        float2 a0 = __half22float2(*(__half2*)&r0.x), b0 = __half22float2(*(__half2*)&r0.y);
        float2 a1 = __half22float2(*(__half2*)&r1.x), b1 = __half22float2(*(__half2*)&r1.y);
        float2 a2 = __half22float2(*(__half2*)&r2.x), b2 = __half22float2(*(__half2*)&r2.y);
        float2 a3 = __half22float2(*(__half2*)&r3.x), b3 = __half22float2(*(__half2*)&r3.y);
        acc.x += p0 * a0.x + p1 * a1.x + p2 * a2.x + p3 * a3.x;
        acc.y += p0 * a0.y + p1 * a1.y + p2 * a2.y + p3 * a3.y;
        acc.z += p0 * b0.x + p1 * b1.x + p2 * b2.x + p3 * b3.x;
        acc.w += p0 * b0.y + p1 * b1.y + p2 * b2.y + p3 * b3.y;
    }
    // scalar tail (<= 3)
    for (; j < end; j++) {
        int s = g_csr_src[j];
        float p = __ldg(&g_pe[j]);
        uint2 raw = *(const uint2*)(Hh + (size_t)s * DD + lane * 4);
        float2 f01 = __half22float2(*(__half2*)&raw.x);
        float2 f23 = __half22float2(*(__half2*)&raw.y);
        z += p;
        acc.x += p * f01.x; acc.y += p * f01.y;
        acc.z += p * f23.x; acc.w += p * f23.y;
    }

    float inv = 1.f / (z + 1e-16f);
    float4 bv = ((const float4*)b)[lane];
    float4 o4 = make_float4(acc.x * inv + bv.x, acc.y * inv + bv.y,
                            acc.z * inv + bv.z, acc.w * inv + bv.w);
    if (do_relu) {
        o4.x = fmaxf(o4.x, 0.f); o4.y = fmaxf(o4.y, 0.f);
        o4.z = fmaxf(o4.z, 0.f); o4.w = fmaxf(o4.w, 0.f);
    }
    ((float4*)(out + (size_t)node * DD))[lane] = o4;
}

// ---------------- host orchestration ----------------------------------------
extern "C" void kernel_launch(void* const* d_in, const int* in_sizes, int n_in,
                              void* d_out, int out_size) {
    const float* x   = (const float*)d_in[0];
    const int*   ei  = (const int*)d_in[1];   // int32 (jax default x64-disabled)
    const float* W1  = (const float*)d_in[2];
    const float* as1 = (const float*)d_in[3];
    const float* ad1 = (const float*)d_in[4];
    const float* b1  = (const float*)d_in[5];
    const float* W2  = (const float*)d_in[6];
    const float* as2 = (const float*)d_in[7];
    const float* ad2 = (const float*)d_in[8];
    const float* b2  = (const float*)d_in[9];
    float*       out = (float*)d_out;

    static cudaStream_t s2 = nullptr;
    static cudaEvent_t ev_fork = nullptr, ev_join = nullptr;
    if (!s2) {
        cudaFuncSetAttribute(gemm128, cudaFuncAttributeMaxDynamicSharedMemorySize,
                             2 * 128 * 128 * sizeof(float));
        cudaStreamCreateWithFlags(&s2, cudaStreamNonBlocking);
        cudaEventCreateWithFlags(&ev_fork, cudaEventDisableTiming);
        cudaEventCreateWithFlags(&ev_join, cudaEventDisableTiming);
    }

    __half* hh = nullptr;
    float* x1 = nullptr;
    cudaGetSymbolAddress((void**)&hh, g_hh);
    cudaGetSymbolAddress((void**)&x1, g_x1);

    const int GEMM_SMEM = 2 * 128 * 128 * sizeof(float);

    // fork: CSR build (independent of GEMM1) on side stream
    cudaEventRecord(ev_fork, 0);
    cudaStreamWaitEvent(s2, ev_fork, 0);
    zero_deg<<<(NN + 255) / 256, 256, 0, s2>>>();
    csr_hist<<<(ET + 255) / 256, 256, 0, s2>>>(ei);
    csr_scan<<<1, 1024, 0, s2>>>();
    csr_scatter<<<(ET + 255) / 256, 256, 0, s2>>>(ei);
    cudaEventRecord(ev_join, s2);

    // layer-1 GEMM overlaps the CSR build
    gemm128<<<(NN + 127) / 128, 256, GEMM_SMEM>>>(x, W1, hh, as1, ad1);

    // join before edge_p (needs CSR + scores)
    cudaStreamWaitEvent(0, ev_join, 0);
    edge_p<<<(ET + 255) / 256, 256>>>();
    aggregate<<<(NN * 32 + 255) / 256, 256>>>(hh, b1, x1, 1);

    // layer 2
    gemm128<<<(NN + 127) / 128, 256, GEMM_SMEM>>>(x1, W2, hh, as2, ad2);
    edge_p<<<(ET + 255) / 256, 256>>>();
    aggregate<<<(NN * 32 + 255) / 256, 256>>>(hh, b2, out, 0);
}